// round 15
// baseline (speedup 1.0000x reference)
#include <cuda_runtime.h>
#include <cuda_fp16.h>
#include <cstdint>

#define BB   2
#define LL   2048
#define DD   1024
#define HH   16

// Scratch (allocation-free: device globals) — fp16 operands
__device__ __half g_xt[(size_t)BB * LL * DD];
__device__ __half g_qkv[(size_t)BB * LL * 3 * DD];
__device__ __half g_att[(size_t)BB * LL * DD];
__device__ __half g_wtin[(size_t)3 * DD * DD];
__device__ __half g_wtout[(size_t)DD * DD];

// ---------------------------------------------------------------------------
// helpers
// ---------------------------------------------------------------------------
__device__ __forceinline__ float ex2f(float x) {
    float y;
    asm("ex2.approx.f32 %0, %1;" : "=f"(y) : "f"(x));
    return y;
}

__device__ __forceinline__ uint32_t pack_f16x2(float lo, float hi) {
    uint32_t r;
    asm("cvt.rn.f16x2.f32 %0, %1, %2;" : "=r"(r) : "f"(hi), "f"(lo));
    return r;
}

__device__ __forceinline__ void mma_f16(float* d, const uint32_t* a,
                                        const uint32_t* b) {
    asm volatile(
        "mma.sync.aligned.m16n8k16.row.col.f32.f16.f16.f32 "
        "{%0,%1,%2,%3}, {%4,%5,%6,%7}, {%8,%9}, {%0,%1,%2,%3};"
        : "+f"(d[0]), "+f"(d[1]), "+f"(d[2]), "+f"(d[3])
        : "r"(a[0]), "r"(a[1]), "r"(a[2]), "r"(a[3]),
          "r"(b[0]), "r"(b[1]));
}

__device__ __forceinline__ void ldsm_x4(uint32_t* r, uint32_t addr) {
    asm volatile(
        "ldmatrix.sync.aligned.m8n8.x4.shared.b16 {%0,%1,%2,%3}, [%4];"
        : "=r"(r[0]), "=r"(r[1]), "=r"(r[2]), "=r"(r[3]) : "r"(addr));
}
__device__ __forceinline__ void ldsm_x4_t(uint32_t* r, uint32_t addr) {
    asm volatile(
        "ldmatrix.sync.aligned.m8n8.x4.trans.shared.b16 {%0,%1,%2,%3}, [%4];"
        : "=r"(r[0]), "=r"(r[1]), "=r"(r[2]), "=r"(r[3]) : "r"(addr));
}

__device__ __forceinline__ uint32_t smem_u32(const void* p) {
    uint32_t a;
    asm("{ .reg .u64 t; cvta.to.shared.u64 t, %1; cvt.u32.u64 %0, t; }"
        : "=r"(a) : "l"(p));
    return a;
}

#define CP_ASYNC16(dst, src) \
    asm volatile("cp.async.cg.shared.global [%0], [%1], 16;" \
                 :: "r"(dst), "l"(src))
#define CP_COMMIT() asm volatile("cp.async.commit_group;")
#define CP_WAIT(n)  asm volatile("cp.async.wait_group %0;" :: "n"(n))

// ---------------------------------------------------------------------------
__global__ __launch_bounds__(256) void f32_to_f16_kernel(
    const float* __restrict__ in, __half* __restrict__ out, int n4)
{
    int i = blockIdx.x * blockDim.x + threadIdx.x;
    if (i < n4) {
        float4 v = ((const float4*)in)[i];
        ((__half2*)out)[2 * i]     = __floats2half2_rn(v.x, v.y);
        ((__half2*)out)[2 * i + 1] = __floats2half2_rn(v.z, v.w);
    }
}

__global__ __launch_bounds__(256) void transpose_f16_kernel(
    const float* __restrict__ in, __half* __restrict__ out, int R, int C)
{
    __shared__ float tile[32][33];
    int bx = blockIdx.x * 32, by = blockIdx.y * 32;
    int x = bx + threadIdx.x;
    #pragma unroll
    for (int i = 0; i < 32; i += 8) {
        int y = by + threadIdx.y + i;
        tile[threadIdx.y + i][threadIdx.x] = in[(size_t)y * C + x];
    }
    __syncthreads();
    int ox = by + threadIdx.x;
    #pragma unroll
    for (int i = 0; i < 32; i += 8) {
        int oy = bx + threadIdx.y + i;
        out[(size_t)oy * R + ox] = __float2half(tile[threadIdx.x][threadIdx.y + i]);
    }
}

// ---------------------------------------------------------------------------
// fp16 mma.sync GEMM: C[M,N] = A[M,K] @ Bt[N,K]^T + bias[N]
// CTA 128x128, 256 threads, warp tile 64x32, BK=32, 4-stage cp.async.
// ---------------------------------------------------------------------------
__global__ __launch_bounds__(256, 2) void gemm_f16_kernel(
    const __half* __restrict__ A, const __half* __restrict__ Bt,
    const float* __restrict__ bias, float* __restrict__ Cf,
    __half* __restrict__ Ch, int M, int N, int K, int round_out)
{
    extern __shared__ uint32_t smem[];
    const uint32_t sbase = smem_u32(smem);

    const int tid = threadIdx.x;
    const int wid = tid >> 5;
    const int lid = tid & 31;
    const int gid = lid >> 2;
    const int tig = lid & 3;
    const int lt  = lid >> 3;
    const int lr  = lid & 7;

    const int bm = blockIdx.y * 128;
    const int bn = blockIdx.x * 128;

    const int mbase = (wid & 1) * 64;
    const int nbase = (wid >> 1) * 32;

    const uint32_t a_off = (uint32_t)((mbase + (lt & 1) * 8 + lr) * 80
                                      + (lt >> 1) * 16);
    const uint32_t b_off = (uint32_t)((nbase + (lt >> 1) * 8 + lr) * 80
                                      + (lt & 1) * 16);

    float acc[4][4][4];
    #pragma unroll
    for (int i = 0; i < 4; i++)
        #pragma unroll
        for (int j = 0; j < 4; j++)
            #pragma unroll
            for (int e = 0; e < 4; e++) acc[i][j][e] = 0.0f;

    const int NC = K >> 5;
    constexpr uint32_t ASTG = 128 * 80;
    constexpr uint32_t BBASE = 4 * ASTG;

    auto issue = [&](int c) {
        const int p = c & 3;
        const __half* Ab = A  + (size_t)bm * K + c * 32;
        const __half* Bb = Bt + (size_t)bn * K + c * 32;
        const uint32_t aoff = sbase + (uint32_t)p * ASTG;
        const uint32_t boff = sbase + BBASE + (uint32_t)p * ASTG;
        #pragma unroll
        for (int i = 0; i < 2; i++) {
            int seg = tid + i * 256;
            int r = seg >> 2;
            int cc = seg & 3;
            uint32_t d = (uint32_t)(r * 80 + cc * 16);
            CP_ASYNC16(aoff + d, Ab + (size_t)r * K + cc * 8);
            CP_ASYNC16(boff + d, Bb + (size_t)r * K + cc * 8);
        }
        CP_COMMIT();
    };

    issue(0);
    issue(1);
    issue(2);

    for (int c = 0; c < NC; c++) {
        if (c <= NC - 3)      { CP_WAIT(2); }
        else if (c == NC - 2) { CP_WAIT(1); }
        else                  { CP_WAIT(0); }
        __syncthreads();
        if (c + 3 < NC) issue(c + 3);

        const uint32_t asb = sbase + (uint32_t)(c & 3) * ASTG + a_off;
        const uint32_t bsb = sbase + BBASE + (uint32_t)(c & 3) * ASTG + b_off;
        #pragma unroll
        for (int ks = 0; ks < 2; ks++) {
            const uint32_t k0b = (uint32_t)(ks * 32);
            uint32_t af[4][4], bf[2][4];
            #pragma unroll
            for (int i = 0; i < 4; i++)
                ldsm_x4(af[i], asb + k0b + (uint32_t)(i * 16 * 80));
            #pragma unroll
            for (int p = 0; p < 2; p++)
                ldsm_x4(bf[p], bsb + k0b + (uint32_t)(p * 16 * 80));
            #pragma unroll
            for (int i = 0; i < 4; i++)
                #pragma unroll
                for (int j = 0; j < 4; j++)
                    mma_f16(acc[i][j], af[i], bf[j >> 1] + (j & 1) * 2);
        }
    }

    #pragma unroll
    for (int j = 0; j < 4; j++) {
        const int col = bn + nbase + j * 8 + 2 * tig;
        const float bi0 = __ldg(bias + col);
        const float bi1 = __ldg(bias + col + 1);
        #pragma unroll
        for (int i = 0; i < 4; i++) {
            const int row0 = bm + mbase + i * 16 + gid;
            if (round_out) {
                *(uint32_t*)(Ch + (size_t)row0 * N + col) =
                    pack_f16x2(acc[i][j][0] + bi0, acc[i][j][1] + bi1);
                *(uint32_t*)(Ch + (size_t)(row0 + 8) * N + col) =
                    pack_f16x2(acc[i][j][2] + bi0, acc[i][j][3] + bi1);
            } else {
                float2 v0 = { acc[i][j][0] + bi0, acc[i][j][1] + bi1 };
                float2 v1 = { acc[i][j][2] + bi0, acc[i][j][3] + bi1 };
                *(float2*)(Cf + (size_t)row0 * N + col) = v0;
                *(float2*)(Cf + (size_t)(row0 + 8) * N + col) = v1;
            }
        }
    }
}

// ---------------------------------------------------------------------------
// Fused causal ALiBi attention, fp16 m16n8k16 mma.sync.
// 128-query tiles; K/V staged in 128-KEY double buffers (one cp.async
// batch + one barrier per 128 keys, two 64-key compute halves per stage).
// Fixed softmax shift (m=0), register-level P, per-thread l accumulation.
// ---------------------------------------------------------------------------
__global__ __launch_bounds__(256, 2) void attn_f16_kernel(
    const __half* __restrict__ qkv, __half* __restrict__ out)
{
    extern __shared__ uint32_t sm[];
    const uint32_t qb  = smem_u32(sm);            // Q  [128][72 f16]
    const uint32_t kb0 = qb  + 18432;             // K0 [128][72]
    const uint32_t kb1 = kb0 + 18432;             // K1
    const uint32_t vb0 = kb1 + 18432;             // V0 [128][72]
    const uint32_t vb1 = vb0 + 18432;             // V1

    const int tid = threadIdx.x;
    const int wid = tid >> 5;
    const int lid = tid & 31;
    const int gid = lid >> 2;
    const int tig = lid & 3;
    const int lt  = lid >> 3;
    const int lr  = lid & 7;

    const int qt = (int)gridDim.x - 1 - (int)blockIdx.x;  // heavy tiles first
    const int bh = blockIdx.y;
    const int b  = bh >> 4;
    const int h  = bh & 15;

    constexpr float L2E = 1.4426950408889634f;
    const float slope2 = exp2f(-0.5f * (float)(h + 1)) * L2E;
    const float scale2 = 0.125f * L2E;

    const __half* base = qkv + (size_t)b * LL * 3072 + h * 64;

    const int mbase = wid * 16;
    const int row0g = qt * 128 + mbase + gid;

    const uint32_t a_off = (uint32_t)((mbase + (lt & 1) * 8 + lr) * 144
                                      + (lt >> 1) * 16);      // Q A frags
    const uint32_t p_off = (uint32_t)(((lt & 1) * 8 + lr) * 144
                                      + (lt >> 1) * 16);      // V row-local
    const uint32_t k_off = (uint32_t)(((lt >> 1) * 8 + lr) * 144
                                      + (lt & 1) * 16);       // K B frags

    // load 128 keys of K and V into (kb, vb)
    auto issue_kv = [&](int ch, uint32_t kb, uint32_t vb) {
        #pragma unroll
        for (int i = 0; i < 4; i++) {
            int seg = tid + i * 256;   // 0..1023 = 128 rows x 8 chunks
            int r = seg >> 3;
            int c = seg & 7;
            const __half* rp = base + (size_t)(ch * 128 + r) * 3072;
            uint32_t d = (uint32_t)(r * 144 + c * 16);
            CP_ASYNC16(kb + d, rp + 1024 + c * 8);
            CP_ASYNC16(vb + d, rp + 2048 + c * 8);
        }
        CP_COMMIT();
    };

    // prologue: Q tile + KV chunk 0
    #pragma unroll
    for (int i = 0; i < 4; i++) {
        int seg = tid + i * 256;
        int r = seg >> 3;
        int c = seg & 7;
        CP_ASYNC16(qb + (uint32_t)(r * 144 + c * 16),
                   base + (size_t)(qt * 128 + r) * 3072 + c * 8);
    }
    CP_COMMIT();
    issue_kv(0, kb0, vb0);
    CP_WAIT(0);
    __syncthreads();

    // hoist Q fragments (constant across chunks)
    uint32_t qf[4][4];
    #pragma unroll
    for (int ks = 0; ks < 4; ks++)
        ldsm_x4(qf[ks], qb + a_off + (uint32_t)(ks * 32));

    float l0 = 0.0f, l1 = 0.0f;
    float O[8][4];
    #pragma unroll
    for (int j = 0; j < 8; j++)
        #pragma unroll
        for (int e = 0; e < 4; e++) O[j][e] = 0.0f;

    const float sq0 = slope2 * (float)row0g;
    const float sq1 = slope2 * (float)(row0g + 8);

    // compute one 64-key half starting at global key index kt*64,
    // reading from (kb64, vb64) = base of that 64-row half
    auto compute64 = [&](int kt, uint32_t kb64, uint32_t vb64, bool MASKED) {
        float s[8][4];
        #pragma unroll
        for (int j = 0; j < 8; j++)
            #pragma unroll
            for (int e = 0; e < 4; e++) s[j][e] = 0.0f;

        #pragma unroll
        for (int ks = 0; ks < 4; ks++) {
            const uint32_t k0b = (uint32_t)(ks * 32);
            uint32_t bf[4][4];
            #pragma unroll
            for (int g = 0; g < 4; g++)
                ldsm_x4(bf[g], kb64 + k_off + k0b + (uint32_t)(g * 16 * 144));
            #pragma unroll
            for (int j = 0; j < 8; j++)
                mma_f16(s[j], qf[ks], bf[j >> 1] + (j & 1) * 2);
        }

        const int kc0 = kt * 64 + 2 * tig;
        #pragma unroll
        for (int j = 0; j < 8; j++) {
            const float sk0 = slope2 * (float)(kc0 + j * 8);
            const float sk1 = sk0 + slope2;
            float v0 = s[j][0] * scale2 + sk0 - sq0;
            float v1 = s[j][1] * scale2 + sk1 - sq0;
            float v2 = s[j][2] * scale2 + sk0 - sq1;
            float v3 = s[j][3] * scale2 + sk1 - sq1;
            if (MASKED) {
                int kg0 = kc0 + j * 8, kg1 = kg0 + 1;
                v0 = (kg0 <= row0g)     ? v0 : -1e30f;
                v1 = (kg1 <= row0g)     ? v1 : -1e30f;
                v2 = (kg0 <= row0g + 8) ? v2 : -1e30f;
                v3 = (kg1 <= row0g + 8) ? v3 : -1e30f;
            }
            s[j][0] = ex2f(v0);
            s[j][1] = ex2f(v1);
            s[j][2] = ex2f(v2);
            s[j][3] = ex2f(v3);
            l0 += s[j][0] + s[j][1];
            l1 += s[j][2] + s[j][3];
        }

        #pragma unroll
        for (int ks = 0; ks < 4; ks++) {
            uint32_t a[4], bf[4][4];
            a[0] = pack_f16x2(s[2 * ks][0],     s[2 * ks][1]);
            a[1] = pack_f16x2(s[2 * ks][2],     s[2 * ks][3]);
            a[2] = pack_f16x2(s[2 * ks + 1][0], s[2 * ks + 1][1]);
            a[3] = pack_f16x2(s[2 * ks + 1][2], s[2 * ks + 1][3]);
            #pragma unroll
            for (int g = 0; g < 4; g++)
                ldsm_x4_t(bf[g], vb64 + p_off + (uint32_t)(ks * 16 * 144 + g * 32));
            #pragma unroll
            for (int j = 0; j < 8; j++)
                mma_f16(O[j], a, bf[j >> 1] + (j & 1) * 2);
        }
    };

    const int nchunks = qt + 1;   // 128-key chunks; keys 0 .. qt*128+127

    for (int ch = 0; ch < nchunks; ch++) {
        const uint32_t kb = (ch & 1) ? kb1 : kb0;
        const uint32_t vb = (ch & 1) ? vb1 : vb0;
        if (ch + 1 < nchunks)
            issue_kv(ch + 1, (ch & 1) ? kb0 : kb1, (ch & 1) ? vb0 : vb1);

        const bool MASKED = (ch == nchunks - 1);
        compute64(ch * 2 + 0, kb, vb, MASKED);
        compute64(ch * 2 + 1, kb + 64u * 144u, vb + 64u * 144u, MASKED);

        if (ch + 1 < nchunks) {
            CP_WAIT(0);
            __syncthreads();
        }
    }

    // epilogue: reduce l across the quad once
    l0 += __shfl_xor_sync(0xffffffffu, l0, 1);
    l0 += __shfl_xor_sync(0xffffffffu, l0, 2);
    l1 += __shfl_xor_sync(0xffffffffu, l1, 1);
    l1 += __shfl_xor_sync(0xffffffffu, l1, 2);
    const float inv0 = 1.0f / l0;
    const float inv1 = 1.0f / l1;

    #pragma unroll
    for (int j = 0; j < 8; j++) {
        const int col = h * 64 + j * 8 + 2 * tig;
        *(uint32_t*)(out + ((size_t)b * LL + row0g) * DD + col) =
            pack_f16x2(O[j][0] * inv0, O[j][1] * inv0);
        *(uint32_t*)(out + ((size_t)b * LL + row0g + 8) * DD + col) =
            pack_f16x2(O[j][2] * inv1, O[j][3] * inv1);
    }
}

// ---------------------------------------------------------------------------
extern "C" void kernel_launch(void* const* d_in, const int* in_sizes, int n_in,
                              void* d_out, int out_size)
{
    const float* x     = (const float*)d_in[0];
    const float* w_in  = (const float*)d_in[1];
    const float* b_in  = (const float*)d_in[2];
    const float* w_out = (const float*)d_in[3];
    const float* b_out = (const float*)d_in[4];
    float* out = (float*)d_out;

    __half *xt, *qkv, *att, *wtin, *wtout;
    cudaGetSymbolAddress((void**)&xt, g_xt);
    cudaGetSymbolAddress((void**)&qkv, g_qkv);
    cudaGetSymbolAddress((void**)&att, g_att);
    cudaGetSymbolAddress((void**)&wtin, g_wtin);
    cudaGetSymbolAddress((void**)&wtout, g_wtout);

    const int M = BB * LL;
    const int GEMM_SMEM = 4 * 2 * 128 * 80;   // 81920
    const int ATTN_SMEM = 5 * 18432;          // 92160
    static bool attr_set = false;
    if (!attr_set) {
        cudaFuncSetAttribute(gemm_f16_kernel,
                             cudaFuncAttributeMaxDynamicSharedMemorySize, GEMM_SMEM);
        cudaFuncSetAttribute(attn_f16_kernel,
                             cudaFuncAttributeMaxDynamicSharedMemorySize, ATTN_SMEM);
        attr_set = true;
    }

    // 0) Convert x to fp16; transpose+convert weights
    {
        int n4 = M * DD / 4;
        f32_to_f16_kernel<<<(n4 + 255) / 256, 256>>>(x, xt, n4);
        dim3 blk(32, 8);
        transpose_f16_kernel<<<dim3(3 * DD / 32, DD / 32), blk>>>(w_in, wtin, DD, 3 * DD);
        transpose_f16_kernel<<<dim3(DD / 32, DD / 32), blk>>>(w_out, wtout, DD, DD);
    }

    // 1) QKV projection (fp16 out)
    {
        dim3 grid(3 * DD / 128, M / 128);
        gemm_f16_kernel<<<grid, 256, GEMM_SMEM>>>(xt, wtin, b_in, nullptr, qkv,
                                                  M, 3 * DD, DD, 1);
    }

    // 2) Fused causal ALiBi attention (fp16 out)
    {
        dim3 grid(LL / 128, BB * HH);
        attn_f16_kernel<<<grid, 256, ATTN_SMEM>>>(qkv, att);
    }

    // 3) Output projection (fp32 out)
    {
        dim3 grid(DD / 128, M / 128);
        gemm_f16_kernel<<<grid, 256, GEMM_SMEM>>>(att, wtout, b_out, out, nullptr,
                                                  M, DD, DD, 0);
    }
}

// round 16
// speedup vs baseline: 1.0653x; 1.0653x over previous
#include <cuda_runtime.h>
#include <cuda_fp16.h>
#include <cstdint>

#define BB   2
#define LL   2048
#define DD   1024
#define HH   16

// Scratch (allocation-free: device globals) — fp16 operands
__device__ __half g_xt[(size_t)BB * LL * DD];
__device__ __half g_qkv[(size_t)BB * LL * 3 * DD];
__device__ __half g_att[(size_t)BB * LL * DD];
__device__ __half g_wtin[(size_t)3 * DD * DD];
__device__ __half g_wtout[(size_t)DD * DD];

// ---------------------------------------------------------------------------
// helpers
// ---------------------------------------------------------------------------
__device__ __forceinline__ float ex2f(float x) {
    float y;
    asm("ex2.approx.f32 %0, %1;" : "=f"(y) : "f"(x));
    return y;
}

__device__ __forceinline__ uint32_t pack_f16x2(float lo, float hi) {
    uint32_t r;
    asm("cvt.rn.f16x2.f32 %0, %1, %2;" : "=r"(r) : "f"(hi), "f"(lo));
    return r;
}

__device__ __forceinline__ void mma_f16(float* d, const uint32_t* a,
                                        const uint32_t* b) {
    asm volatile(
        "mma.sync.aligned.m16n8k16.row.col.f32.f16.f16.f32 "
        "{%0,%1,%2,%3}, {%4,%5,%6,%7}, {%8,%9}, {%0,%1,%2,%3};"
        : "+f"(d[0]), "+f"(d[1]), "+f"(d[2]), "+f"(d[3])
        : "r"(a[0]), "r"(a[1]), "r"(a[2]), "r"(a[3]),
          "r"(b[0]), "r"(b[1]));
}

__device__ __forceinline__ void ldsm_x4(uint32_t* r, uint32_t addr) {
    asm volatile(
        "ldmatrix.sync.aligned.m8n8.x4.shared.b16 {%0,%1,%2,%3}, [%4];"
        : "=r"(r[0]), "=r"(r[1]), "=r"(r[2]), "=r"(r[3]) : "r"(addr));
}
__device__ __forceinline__ void ldsm_x4_t(uint32_t* r, uint32_t addr) {
    asm volatile(
        "ldmatrix.sync.aligned.m8n8.x4.trans.shared.b16 {%0,%1,%2,%3}, [%4];"
        : "=r"(r[0]), "=r"(r[1]), "=r"(r[2]), "=r"(r[3]) : "r"(addr));
}

__device__ __forceinline__ uint32_t smem_u32(const void* p) {
    uint32_t a;
    asm("{ .reg .u64 t; cvta.to.shared.u64 t, %1; cvt.u32.u64 %0, t; }"
        : "=r"(a) : "l"(p));
    return a;
}

#define CP_ASYNC16(dst, src) \
    asm volatile("cp.async.cg.shared.global [%0], [%1], 16;" \
                 :: "r"(dst), "l"(src))
#define CP_COMMIT() asm volatile("cp.async.commit_group;")
#define CP_WAIT(n)  asm volatile("cp.async.wait_group %0;" :: "n"(n))

// ---------------------------------------------------------------------------
__global__ __launch_bounds__(256) void f32_to_f16_kernel(
    const float* __restrict__ in, __half* __restrict__ out, int n4)
{
    int i = blockIdx.x * blockDim.x + threadIdx.x;
    if (i < n4) {
        float4 v = ((const float4*)in)[i];
        ((__half2*)out)[2 * i]     = __floats2half2_rn(v.x, v.y);
        ((__half2*)out)[2 * i + 1] = __floats2half2_rn(v.z, v.w);
    }
}

__global__ __launch_bounds__(256) void transpose_f16_kernel(
    const float* __restrict__ in, __half* __restrict__ out, int R, int C)
{
    __shared__ float tile[32][33];
    int bx = blockIdx.x * 32, by = blockIdx.y * 32;
    int x = bx + threadIdx.x;
    #pragma unroll
    for (int i = 0; i < 32; i += 8) {
        int y = by + threadIdx.y + i;
        tile[threadIdx.y + i][threadIdx.x] = in[(size_t)y * C + x];
    }
    __syncthreads();
    int ox = by + threadIdx.x;
    #pragma unroll
    for (int i = 0; i < 32; i += 8) {
        int oy = bx + threadIdx.y + i;
        out[(size_t)oy * R + ox] = __float2half(tile[threadIdx.x][threadIdx.y + i]);
    }
}

// ---------------------------------------------------------------------------
// fp16 mma.sync GEMM: C[M,N] = A[M,K] @ Bt[N,K]^T + bias[N]
// CTA 128x128, 256 threads, warp tile 64x32, BK=64 (4 x k16 steps),
// 3-stage cp.async — HALF the barriers of the BK=32 version.
// smem row stride 144 B (proven conflict-free ldmatrix pattern).
// ---------------------------------------------------------------------------
__global__ __launch_bounds__(256, 2) void gemm_f16_kernel(
    const __half* __restrict__ A, const __half* __restrict__ Bt,
    const float* __restrict__ bias, float* __restrict__ Cf,
    __half* __restrict__ Ch, int M, int N, int K, int round_out)
{
    extern __shared__ uint32_t smem[];
    const uint32_t sbase = smem_u32(smem);

    const int tid = threadIdx.x;
    const int wid = tid >> 5;
    const int lid = tid & 31;
    const int gid = lid >> 2;
    const int tig = lid & 3;
    const int lt  = lid >> 3;
    const int lr  = lid & 7;

    const int bm = blockIdx.y * 128;
    const int bn = blockIdx.x * 128;

    const int mbase = (wid & 1) * 64;
    const int nbase = (wid >> 1) * 32;

    const uint32_t a_off = (uint32_t)((mbase + (lt & 1) * 8 + lr) * 144
                                      + (lt >> 1) * 16);
    const uint32_t b_off = (uint32_t)((nbase + (lt >> 1) * 8 + lr) * 144
                                      + (lt & 1) * 16);

    float acc[4][4][4];
    #pragma unroll
    for (int i = 0; i < 4; i++)
        #pragma unroll
        for (int j = 0; j < 4; j++)
            #pragma unroll
            for (int e = 0; e < 4; e++) acc[i][j][e] = 0.0f;

    const int NC = K >> 6;                     // 64-wide K chunks
    constexpr uint32_t ASTG = 128 * 144;       // 18432 B per operand stage
    constexpr uint32_t BBASE = 3 * ASTG;

    auto issue = [&](int c) {
        const int p = c % 3;
        const __half* Ab = A  + (size_t)bm * K + c * 64;
        const __half* Bb = Bt + (size_t)bn * K + c * 64;
        const uint32_t aoff = sbase + (uint32_t)p * ASTG;
        const uint32_t boff = sbase + BBASE + (uint32_t)p * ASTG;
        #pragma unroll
        for (int i = 0; i < 4; i++) {
            int seg = tid + i * 256;           // 0..1023 = 128 rows x 8 chunks
            int r = seg >> 3;
            int cc = seg & 7;
            uint32_t d = (uint32_t)(r * 144 + cc * 16);
            CP_ASYNC16(aoff + d, Ab + (size_t)r * K + cc * 8);
            CP_ASYNC16(boff + d, Bb + (size_t)r * K + cc * 8);
        }
        CP_COMMIT();
    };

    issue(0);
    issue(1);

    for (int c = 0; c < NC; c++) {
        if (c + 1 < NC) { CP_WAIT(1); } else { CP_WAIT(0); }
        __syncthreads();
        if (c + 2 < NC) issue(c + 2);

        const uint32_t asb = sbase + (uint32_t)(c % 3) * ASTG + a_off;
        const uint32_t bsb = sbase + BBASE + (uint32_t)(c % 3) * ASTG + b_off;
        #pragma unroll
        for (int ks = 0; ks < 4; ks++) {
            const uint32_t k0b = (uint32_t)(ks * 32);
            uint32_t af[4][4], bf[2][4];
            #pragma unroll
            for (int i = 0; i < 4; i++)
                ldsm_x4(af[i], asb + k0b + (uint32_t)(i * 16 * 144));
            #pragma unroll
            for (int p = 0; p < 2; p++)
                ldsm_x4(bf[p], bsb + k0b + (uint32_t)(p * 16 * 144));
            #pragma unroll
            for (int i = 0; i < 4; i++)
                #pragma unroll
                for (int j = 0; j < 4; j++)
                    mma_f16(acc[i][j], af[i], bf[j >> 1] + (j & 1) * 2);
        }
    }

    #pragma unroll
    for (int j = 0; j < 4; j++) {
        const int col = bn + nbase + j * 8 + 2 * tig;
        const float bi0 = __ldg(bias + col);
        const float bi1 = __ldg(bias + col + 1);
        #pragma unroll
        for (int i = 0; i < 4; i++) {
            const int row0 = bm + mbase + i * 16 + gid;
            if (round_out) {
                *(uint32_t*)(Ch + (size_t)row0 * N + col) =
                    pack_f16x2(acc[i][j][0] + bi0, acc[i][j][1] + bi1);
                *(uint32_t*)(Ch + (size_t)(row0 + 8) * N + col) =
                    pack_f16x2(acc[i][j][2] + bi0, acc[i][j][3] + bi1);
            } else {
                float2 v0 = { acc[i][j][0] + bi0, acc[i][j][1] + bi1 };
                float2 v1 = { acc[i][j][2] + bi0, acc[i][j][3] + bi1 };
                *(float2*)(Cf + (size_t)row0 * N + col) = v0;
                *(float2*)(Cf + (size_t)(row0 + 8) * N + col) = v1;
            }
        }
    }
}

// ---------------------------------------------------------------------------
// Fused causal ALiBi attention (R14 configuration — best measured).
// fp16 m16n8k16, 128-query tiles, 64-key double-buffered chunks,
// fixed softmax shift (m=0), register-level P, per-thread l accumulation.
// ---------------------------------------------------------------------------
__global__ __launch_bounds__(256, 2) void attn_f16_kernel(
    const __half* __restrict__ qkv, __half* __restrict__ out)
{
    extern __shared__ uint32_t sm[];
    const uint32_t qb  = smem_u32(sm);            // Q  [128][72 f16]
    const uint32_t kb0 = qb + 18432;              // K0 [64][72]
    const uint32_t kb1 = kb0 + 9216;              // K1
    const uint32_t vb0 = kb1 + 9216;              // V0 [64][72]
    const uint32_t vb1 = vb0 + 9216;              // V1

    const int tid = threadIdx.x;
    const int wid = tid >> 5;
    const int lid = tid & 31;
    const int gid = lid >> 2;
    const int tig = lid & 3;
    const int lt  = lid >> 3;
    const int lr  = lid & 7;

    const int qt = (int)gridDim.x - 1 - (int)blockIdx.x;  // heavy tiles first
    const int bh = blockIdx.y;
    const int b  = bh >> 4;
    const int h  = bh & 15;

    constexpr float L2E = 1.4426950408889634f;
    const float slope2 = exp2f(-0.5f * (float)(h + 1)) * L2E;
    const float scale2 = 0.125f * L2E;

    const __half* base = qkv + (size_t)b * LL * 3072 + h * 64;

    const int mbase = wid * 16;
    const int row0g = qt * 128 + mbase + gid;

    const uint32_t a_off = (uint32_t)((mbase + (lt & 1) * 8 + lr) * 144
                                      + (lt >> 1) * 16);      // Q A frags
    const uint32_t p_off = (uint32_t)(((lt & 1) * 8 + lr) * 144
                                      + (lt >> 1) * 16);      // V row-local
    const uint32_t k_off = (uint32_t)(((lt >> 1) * 8 + lr) * 144
                                      + (lt & 1) * 16);       // K B frags

    auto issue_kv = [&](int kt, uint32_t kb, uint32_t vb) {
        #pragma unroll
        for (int i = 0; i < 2; i++) {
            int seg = tid + i * 256;
            int r = seg >> 3;
            int c = seg & 7;
            const __half* rp = base + (size_t)(kt * 64 + r) * 3072;
            uint32_t d = (uint32_t)(r * 144 + c * 16);
            CP_ASYNC16(kb + d, rp + 1024 + c * 8);
            CP_ASYNC16(vb + d, rp + 2048 + c * 8);
        }
        CP_COMMIT();
    };

    // prologue: Q tile + KV chunk 0
    #pragma unroll
    for (int i = 0; i < 4; i++) {
        int seg = tid + i * 256;
        int r = seg >> 3;
        int c = seg & 7;
        CP_ASYNC16(qb + (uint32_t)(r * 144 + c * 16),
                   base + (size_t)(qt * 128 + r) * 3072 + c * 8);
    }
    CP_COMMIT();
    issue_kv(0, kb0, vb0);
    CP_WAIT(0);
    __syncthreads();

    // hoist Q fragments (constant across chunks)
    uint32_t qf[4][4];
    #pragma unroll
    for (int ks = 0; ks < 4; ks++)
        ldsm_x4(qf[ks], qb + a_off + (uint32_t)(ks * 32));

    float l0 = 0.0f, l1 = 0.0f;
    float O[8][4];
    #pragma unroll
    for (int j = 0; j < 8; j++)
        #pragma unroll
        for (int e = 0; e < 4; e++) O[j][e] = 0.0f;

    const float sq0 = slope2 * (float)row0g;
    const float sq1 = slope2 * (float)(row0g + 8);

    const int nfull = 2 * qt;
    const int nkt = nfull + 2;

    auto compute = [&](int kt, bool MASKED) {
        const uint32_t kb = (kt & 1) ? kb1 : kb0;
        const uint32_t vb = (kt & 1) ? vb1 : vb0;

        float s[8][4];
        #pragma unroll
        for (int j = 0; j < 8; j++)
            #pragma unroll
            for (int e = 0; e < 4; e++) s[j][e] = 0.0f;

        #pragma unroll
        for (int ks = 0; ks < 4; ks++) {
            const uint32_t k0b = (uint32_t)(ks * 32);
            uint32_t bf[4][4];
            #pragma unroll
            for (int g = 0; g < 4; g++)
                ldsm_x4(bf[g], kb + k_off + k0b + (uint32_t)(g * 16 * 144));
            #pragma unroll
            for (int j = 0; j < 8; j++)
                mma_f16(s[j], qf[ks], bf[j >> 1] + (j & 1) * 2);
        }

        const int kc0 = kt * 64 + 2 * tig;
        #pragma unroll
        for (int j = 0; j < 8; j++) {
            const float sk0 = slope2 * (float)(kc0 + j * 8);
            const float sk1 = sk0 + slope2;
            float v0 = s[j][0] * scale2 + sk0 - sq0;
            float v1 = s[j][1] * scale2 + sk1 - sq0;
            float v2 = s[j][2] * scale2 + sk0 - sq1;
            float v3 = s[j][3] * scale2 + sk1 - sq1;
            if (MASKED) {
                int kg0 = kc0 + j * 8, kg1 = kg0 + 1;
                v0 = (kg0 <= row0g)     ? v0 : -1e30f;
                v1 = (kg1 <= row0g)     ? v1 : -1e30f;
                v2 = (kg0 <= row0g + 8) ? v2 : -1e30f;
                v3 = (kg1 <= row0g + 8) ? v3 : -1e30f;
            }
            s[j][0] = ex2f(v0);
            s[j][1] = ex2f(v1);
            s[j][2] = ex2f(v2);
            s[j][3] = ex2f(v3);
            l0 += s[j][0] + s[j][1];
            l1 += s[j][2] + s[j][3];
        }

        #pragma unroll
        for (int ks = 0; ks < 4; ks++) {
            uint32_t a[4], bf[4][4];
            a[0] = pack_f16x2(s[2 * ks][0],     s[2 * ks][1]);
            a[1] = pack_f16x2(s[2 * ks][2],     s[2 * ks][3]);
            a[2] = pack_f16x2(s[2 * ks + 1][0], s[2 * ks + 1][1]);
            a[3] = pack_f16x2(s[2 * ks + 1][2], s[2 * ks + 1][3]);
            #pragma unroll
            for (int g = 0; g < 4; g++)
                ldsm_x4_t(bf[g], vb + p_off + (uint32_t)(ks * 16 * 144 + g * 32));
            #pragma unroll
            for (int j = 0; j < 8; j++)
                mma_f16(O[j], a, bf[j >> 1] + (j & 1) * 2);
        }
    };

    for (int kt = 0; kt < nkt; kt++) {
        if (kt + 1 < nkt)
            issue_kv(kt + 1, (kt & 1) ? kb0 : kb1, (kt & 1) ? vb0 : vb1);
        compute(kt, kt >= nfull);
        if (kt + 1 < nkt) {
            CP_WAIT(0);
            __syncthreads();
        }
    }

    l0 += __shfl_xor_sync(0xffffffffu, l0, 1);
    l0 += __shfl_xor_sync(0xffffffffu, l0, 2);
    l1 += __shfl_xor_sync(0xffffffffu, l1, 1);
    l1 += __shfl_xor_sync(0xffffffffu, l1, 2);
    const float inv0 = 1.0f / l0;
    const float inv1 = 1.0f / l1;

    #pragma unroll
    for (int j = 0; j < 8; j++) {
        const int col = h * 64 + j * 8 + 2 * tig;
        *(uint32_t*)(out + ((size_t)b * LL + row0g) * DD + col) =
            pack_f16x2(O[j][0] * inv0, O[j][1] * inv0);
        *(uint32_t*)(out + ((size_t)b * LL + row0g + 8) * DD + col) =
            pack_f16x2(O[j][2] * inv1, O[j][3] * inv1);
    }
}

// ---------------------------------------------------------------------------
extern "C" void kernel_launch(void* const* d_in, const int* in_sizes, int n_in,
                              void* d_out, int out_size)
{
    const float* x     = (const float*)d_in[0];
    const float* w_in  = (const float*)d_in[1];
    const float* b_in  = (const float*)d_in[2];
    const float* w_out = (const float*)d_in[3];
    const float* b_out = (const float*)d_in[4];
    float* out = (float*)d_out;

    __half *xt, *qkv, *att, *wtin, *wtout;
    cudaGetSymbolAddress((void**)&xt, g_xt);
    cudaGetSymbolAddress((void**)&qkv, g_qkv);
    cudaGetSymbolAddress((void**)&att, g_att);
    cudaGetSymbolAddress((void**)&wtin, g_wtin);
    cudaGetSymbolAddress((void**)&wtout, g_wtout);

    const int M = BB * LL;
    const int GEMM_SMEM = 6 * 128 * 144;      // 110592
    const int ATTN_SMEM = 18432 + 4 * 9216;   // 55296
    static bool attr_set = false;
    if (!attr_set) {
        cudaFuncSetAttribute(gemm_f16_kernel,
                             cudaFuncAttributeMaxDynamicSharedMemorySize, GEMM_SMEM);
        cudaFuncSetAttribute(attn_f16_kernel,
                             cudaFuncAttributeMaxDynamicSharedMemorySize, ATTN_SMEM);
        attr_set = true;
    }

    // 0) Convert x to fp16; transpose+convert weights
    {
        int n4 = M * DD / 4;
        f32_to_f16_kernel<<<(n4 + 255) / 256, 256>>>(x, xt, n4);
        dim3 blk(32, 8);
        transpose_f16_kernel<<<dim3(3 * DD / 32, DD / 32), blk>>>(w_in, wtin, DD, 3 * DD);
        transpose_f16_kernel<<<dim3(DD / 32, DD / 32), blk>>>(w_out, wtout, DD, DD);
    }

    // 1) QKV projection (fp16 out)
    {
        dim3 grid(3 * DD / 128, M / 128);
        gemm_f16_kernel<<<grid, 256, GEMM_SMEM>>>(xt, wtin, b_in, nullptr, qkv,
                                                  M, 3 * DD, DD, 1);
    }

    // 2) Fused causal ALiBi attention (fp16 out)
    {
        dim3 grid(LL / 128, BB * HH);
        attn_f16_kernel<<<grid, 256, ATTN_SMEM>>>(qkv, att);
    }

    // 3) Output projection (fp32 out)
    {
        dim3 grid(DD / 128, M / 128);
        gemm_f16_kernel<<<grid, 256, GEMM_SMEM>>>(att, wtout, b_out, out, nullptr,
                                                  M, DD, DD, 0);
    }
}

// round 17
// speedup vs baseline: 1.1490x; 1.0785x over previous
#include <cuda_runtime.h>
#include <cuda_fp16.h>
#include <cstdint>

#define BB   2
#define LL   2048
#define DD   1024
#define HH   16

// Scratch (allocation-free: device globals) — fp16 operands
__device__ __half g_xt[(size_t)BB * LL * DD];
__device__ __half g_qkv[(size_t)BB * LL * 3 * DD];
__device__ __half g_att[(size_t)BB * LL * DD];
__device__ __half g_wtin[(size_t)3 * DD * DD];
__device__ __half g_wtout[(size_t)DD * DD];

// ---------------------------------------------------------------------------
// helpers
// ---------------------------------------------------------------------------
__device__ __forceinline__ float ex2f(float x) {
    float y;
    asm("ex2.approx.f32 %0, %1;" : "=f"(y) : "f"(x));
    return y;
}

__device__ __forceinline__ uint32_t pack_f16x2(float lo, float hi) {
    uint32_t r;
    asm("cvt.rn.f16x2.f32 %0, %1, %2;" : "=r"(r) : "f"(hi), "f"(lo));
    return r;
}

__device__ __forceinline__ void mma_f16(float* d, const uint32_t* a,
                                        const uint32_t* b) {
    asm volatile(
        "mma.sync.aligned.m16n8k16.row.col.f32.f16.f16.f32 "
        "{%0,%1,%2,%3}, {%4,%5,%6,%7}, {%8,%9}, {%0,%1,%2,%3};"
        : "+f"(d[0]), "+f"(d[1]), "+f"(d[2]), "+f"(d[3])
        : "r"(a[0]), "r"(a[1]), "r"(a[2]), "r"(a[3]),
          "r"(b[0]), "r"(b[1]));
}

__device__ __forceinline__ void ldsm_x4(uint32_t* r, uint32_t addr) {
    asm volatile(
        "ldmatrix.sync.aligned.m8n8.x4.shared.b16 {%0,%1,%2,%3}, [%4];"
        : "=r"(r[0]), "=r"(r[1]), "=r"(r[2]), "=r"(r[3]) : "r"(addr));
}
__device__ __forceinline__ void ldsm_x4_t(uint32_t* r, uint32_t addr) {
    asm volatile(
        "ldmatrix.sync.aligned.m8n8.x4.trans.shared.b16 {%0,%1,%2,%3}, [%4];"
        : "=r"(r[0]), "=r"(r[1]), "=r"(r[2]), "=r"(r[3]) : "r"(addr));
}

__device__ __forceinline__ uint32_t smem_u32(const void* p) {
    uint32_t a;
    asm("{ .reg .u64 t; cvta.to.shared.u64 t, %1; cvt.u32.u64 %0, t; }"
        : "=r"(a) : "l"(p));
    return a;
}

#define CP_ASYNC16(dst, src) \
    asm volatile("cp.async.cg.shared.global [%0], [%1], 16;" \
                 :: "r"(dst), "l"(src))
#define CP_COMMIT() asm volatile("cp.async.commit_group;")
#define CP_WAIT(n)  asm volatile("cp.async.wait_group %0;" :: "n"(n))

// ---------------------------------------------------------------------------
__global__ __launch_bounds__(256) void f32_to_f16_kernel(
    const float* __restrict__ in, __half* __restrict__ out, int n4)
{
    int i = blockIdx.x * blockDim.x + threadIdx.x;
    if (i < n4) {
        float4 v = ((const float4*)in)[i];
        ((__half2*)out)[2 * i]     = __floats2half2_rn(v.x, v.y);
        ((__half2*)out)[2 * i + 1] = __floats2half2_rn(v.z, v.w);
    }
}

__global__ __launch_bounds__(256) void transpose_f16_kernel(
    const float* __restrict__ in, __half* __restrict__ out, int R, int C)
{
    __shared__ float tile[32][33];
    int bx = blockIdx.x * 32, by = blockIdx.y * 32;
    int x = bx + threadIdx.x;
    #pragma unroll
    for (int i = 0; i < 32; i += 8) {
        int y = by + threadIdx.y + i;
        tile[threadIdx.y + i][threadIdx.x] = in[(size_t)y * C + x];
    }
    __syncthreads();
    int ox = by + threadIdx.x;
    #pragma unroll
    for (int i = 0; i < 32; i += 8) {
        int oy = bx + threadIdx.y + i;
        out[(size_t)oy * R + ox] = __float2half(tile[threadIdx.x][threadIdx.y + i]);
    }
}

// ---------------------------------------------------------------------------
// fp16 mma.sync GEMM: C[M,N] = A[M,K] @ Bt[N,K]^T + bias[N]
// CTA 128x128, 256 threads, warp tile 64x32, BK=64 (4 x k16 steps),
// 3-stage cp.async. smem row stride 144 B.
// ---------------------------------------------------------------------------
__global__ __launch_bounds__(256, 2) void gemm_f16_kernel(
    const __half* __restrict__ A, const __half* __restrict__ Bt,
    const float* __restrict__ bias, float* __restrict__ Cf,
    __half* __restrict__ Ch, int M, int N, int K, int round_out)
{
    extern __shared__ uint32_t smem[];
    const uint32_t sbase = smem_u32(smem);

    const int tid = threadIdx.x;
    const int wid = tid >> 5;
    const int lid = tid & 31;
    const int gid = lid >> 2;
    const int tig = lid & 3;
    const int lt  = lid >> 3;
    const int lr  = lid & 7;

    const int bm = blockIdx.y * 128;
    const int bn = blockIdx.x * 128;

    const int mbase = (wid & 1) * 64;
    const int nbase = (wid >> 1) * 32;

    const uint32_t a_off = (uint32_t)((mbase + (lt & 1) * 8 + lr) * 144
                                      + (lt >> 1) * 16);
    const uint32_t b_off = (uint32_t)((nbase + (lt >> 1) * 8 + lr) * 144
                                      + (lt & 1) * 16);

    float acc[4][4][4];
    #pragma unroll
    for (int i = 0; i < 4; i++)
        #pragma unroll
        for (int j = 0; j < 4; j++)
            #pragma unroll
            for (int e = 0; e < 4; e++) acc[i][j][e] = 0.0f;

    const int NC = K >> 6;
    constexpr uint32_t ASTG = 128 * 144;
    constexpr uint32_t BBASE = 3 * ASTG;

    auto issue = [&](int c) {
        const int p = c % 3;
        const __half* Ab = A  + (size_t)bm * K + c * 64;
        const __half* Bb = Bt + (size_t)bn * K + c * 64;
        const uint32_t aoff = sbase + (uint32_t)p * ASTG;
        const uint32_t boff = sbase + BBASE + (uint32_t)p * ASTG;
        #pragma unroll
        for (int i = 0; i < 4; i++) {
            int seg = tid + i * 256;
            int r = seg >> 3;
            int cc = seg & 7;
            uint32_t d = (uint32_t)(r * 144 + cc * 16);
            CP_ASYNC16(aoff + d, Ab + (size_t)r * K + cc * 8);
            CP_ASYNC16(boff + d, Bb + (size_t)r * K + cc * 8);
        }
        CP_COMMIT();
    };

    issue(0);
    issue(1);

    for (int c = 0; c < NC; c++) {
        if (c + 1 < NC) { CP_WAIT(1); } else { CP_WAIT(0); }
        __syncthreads();
        if (c + 2 < NC) issue(c + 2);

        const uint32_t asb = sbase + (uint32_t)(c % 3) * ASTG + a_off;
        const uint32_t bsb = sbase + BBASE + (uint32_t)(c % 3) * ASTG + b_off;
        #pragma unroll
        for (int ks = 0; ks < 4; ks++) {
            const uint32_t k0b = (uint32_t)(ks * 32);
            uint32_t af[4][4], bf[2][4];
            #pragma unroll
            for (int i = 0; i < 4; i++)
                ldsm_x4(af[i], asb + k0b + (uint32_t)(i * 16 * 144));
            #pragma unroll
            for (int p = 0; p < 2; p++)
                ldsm_x4(bf[p], bsb + k0b + (uint32_t)(p * 16 * 144));
            #pragma unroll
            for (int i = 0; i < 4; i++)
                #pragma unroll
                for (int j = 0; j < 4; j++)
                    mma_f16(acc[i][j], af[i], bf[j >> 1] + (j & 1) * 2);
        }
    }

    #pragma unroll
    for (int j = 0; j < 4; j++) {
        const int col = bn + nbase + j * 8 + 2 * tig;
        const float bi0 = __ldg(bias + col);
        const float bi1 = __ldg(bias + col + 1);
        #pragma unroll
        for (int i = 0; i < 4; i++) {
            const int row0 = bm + mbase + i * 16 + gid;
            if (round_out) {
                *(uint32_t*)(Ch + (size_t)row0 * N + col) =
                    pack_f16x2(acc[i][j][0] + bi0, acc[i][j][1] + bi1);
                *(uint32_t*)(Ch + (size_t)(row0 + 8) * N + col) =
                    pack_f16x2(acc[i][j][2] + bi0, acc[i][j][3] + bi1);
            } else {
                float2 v0 = { acc[i][j][0] + bi0, acc[i][j][1] + bi1 };
                float2 v1 = { acc[i][j][2] + bi0, acc[i][j][3] + bi1 };
                *(float2*)(Cf + (size_t)row0 * N + col) = v0;
                *(float2*)(Cf + (size_t)(row0 + 8) * N + col) = v1;
            }
        }
    }
}

// ---------------------------------------------------------------------------
// Fused causal ALiBi attention, fp16 m16n8k16.
// LOAD-BALANCED: each CTA processes TWO complementary q-tiles
// (nt-1-bx, then bx) => every CTA does identical total work, and the
// grid (LL/256 x B*H = 256 CTAs) fits in ONE wave at 2 CTAs/SM.
// Fixed softmax shift (m=0), register-level P, per-thread l accumulation,
// 64-key double-buffered K/V via cp.async.
// ---------------------------------------------------------------------------
__global__ __launch_bounds__(256, 2) void attn_f16_kernel(
    const __half* __restrict__ qkv, __half* __restrict__ out)
{
    extern __shared__ uint32_t sm[];
    const uint32_t qb  = smem_u32(sm);            // Q  [128][72 f16]
    const uint32_t kb0 = qb + 18432;              // K0 [64][72]
    const uint32_t kb1 = kb0 + 9216;              // K1
    const uint32_t vb0 = kb1 + 9216;              // V0 [64][72]
    const uint32_t vb1 = vb0 + 9216;              // V1

    const int tid = threadIdx.x;
    const int wid = tid >> 5;
    const int lid = tid & 31;
    const int gid = lid >> 2;
    const int tig = lid & 3;
    const int lt  = lid >> 3;
    const int lr  = lid & 7;

    const int nt = (int)gridDim.x * 2;            // q-tiles per (b,h) = 16
    const int bh = blockIdx.y;
    const int b  = bh >> 4;
    const int h  = bh & 15;

    constexpr float L2E = 1.4426950408889634f;
    const float slope2 = exp2f(-0.5f * (float)(h + 1)) * L2E;
    const float scale2 = 0.125f * L2E;

    const __half* base = qkv + (size_t)b * LL * 3072 + h * 64;

    const int mbase = wid * 16;

    const uint32_t a_off = (uint32_t)((mbase + (lt & 1) * 8 + lr) * 144
                                      + (lt >> 1) * 16);      // Q A frags
    const uint32_t p_off = (uint32_t)(((lt & 1) * 8 + lr) * 144
                                      + (lt >> 1) * 16);      // V row-local
    const uint32_t k_off = (uint32_t)(((lt >> 1) * 8 + lr) * 144
                                      + (lt & 1) * 16);       // K B frags

    auto issue_kv = [&](int kt, uint32_t kb, uint32_t vb) {
        #pragma unroll
        for (int i = 0; i < 2; i++) {
            int seg = tid + i * 256;
            int r = seg >> 3;
            int c = seg & 7;
            const __half* rp = base + (size_t)(kt * 64 + r) * 3072;
            uint32_t d = (uint32_t)(r * 144 + c * 16);
            CP_ASYNC16(kb + d, rp + 1024 + c * 8);
            CP_ASYNC16(vb + d, rp + 2048 + c * 8);
        }
        CP_COMMIT();
    };

    // two complementary tiles: equal total work per CTA
    #pragma unroll 1
    for (int half = 0; half < 2; half++) {
        const int qt = (half == 0) ? (nt - 1 - (int)blockIdx.x)
                                   : (int)blockIdx.x;

        const int row0g = qt * 128 + mbase + gid;
        const float sq0 = slope2 * (float)row0g;
        const float sq1 = slope2 * (float)(row0g + 8);

        // prologue: Q tile + KV chunk 0 (buffers are free: either first use
        // or all warps passed the previous tile's final compute since the
        // loop-end barrier below)
        #pragma unroll
        for (int i = 0; i < 4; i++) {
            int seg = tid + i * 256;
            int r = seg >> 3;
            int c = seg & 7;
            CP_ASYNC16(qb + (uint32_t)(r * 144 + c * 16),
                       base + (size_t)(qt * 128 + r) * 3072 + c * 8);
        }
        CP_COMMIT();
        issue_kv(0, kb0, vb0);
        CP_WAIT(0);
        __syncthreads();

        uint32_t qf[4][4];
        #pragma unroll
        for (int ks = 0; ks < 4; ks++)
            ldsm_x4(qf[ks], qb + a_off + (uint32_t)(ks * 32));

        float l0 = 0.0f, l1 = 0.0f;
        float O[8][4];
        #pragma unroll
        for (int j = 0; j < 8; j++)
            #pragma unroll
            for (int e = 0; e < 4; e++) O[j][e] = 0.0f;

        const int nfull = 2 * qt;
        const int nkt = nfull + 2;

        auto compute = [&](int kt, bool MASKED) {
            const uint32_t kb = (kt & 1) ? kb1 : kb0;
            const uint32_t vb = (kt & 1) ? vb1 : vb0;

            float s[8][4];
            #pragma unroll
            for (int j = 0; j < 8; j++)
                #pragma unroll
                for (int e = 0; e < 4; e++) s[j][e] = 0.0f;

            #pragma unroll
            for (int ks = 0; ks < 4; ks++) {
                const uint32_t k0b = (uint32_t)(ks * 32);
                uint32_t bf[4][4];
                #pragma unroll
                for (int g = 0; g < 4; g++)
                    ldsm_x4(bf[g], kb + k_off + k0b + (uint32_t)(g * 16 * 144));
                #pragma unroll
                for (int j = 0; j < 8; j++)
                    mma_f16(s[j], qf[ks], bf[j >> 1] + (j & 1) * 2);
            }

            const int kc0 = kt * 64 + 2 * tig;
            #pragma unroll
            for (int j = 0; j < 8; j++) {
                const float sk0 = slope2 * (float)(kc0 + j * 8);
                const float sk1 = sk0 + slope2;
                float v0 = s[j][0] * scale2 + sk0 - sq0;
                float v1 = s[j][1] * scale2 + sk1 - sq0;
                float v2 = s[j][2] * scale2 + sk0 - sq1;
                float v3 = s[j][3] * scale2 + sk1 - sq1;
                if (MASKED) {
                    int kg0 = kc0 + j * 8, kg1 = kg0 + 1;
                    v0 = (kg0 <= row0g)     ? v0 : -1e30f;
                    v1 = (kg1 <= row0g)     ? v1 : -1e30f;
                    v2 = (kg0 <= row0g + 8) ? v2 : -1e30f;
                    v3 = (kg1 <= row0g + 8) ? v3 : -1e30f;
                }
                s[j][0] = ex2f(v0);
                s[j][1] = ex2f(v1);
                s[j][2] = ex2f(v2);
                s[j][3] = ex2f(v3);
                l0 += s[j][0] + s[j][1];
                l1 += s[j][2] + s[j][3];
            }

            #pragma unroll
            for (int ks = 0; ks < 4; ks++) {
                uint32_t a[4], bf[4][4];
                a[0] = pack_f16x2(s[2 * ks][0],     s[2 * ks][1]);
                a[1] = pack_f16x2(s[2 * ks][2],     s[2 * ks][3]);
                a[2] = pack_f16x2(s[2 * ks + 1][0], s[2 * ks + 1][1]);
                a[3] = pack_f16x2(s[2 * ks + 1][2], s[2 * ks + 1][3]);
                #pragma unroll
                for (int g = 0; g < 4; g++)
                    ldsm_x4_t(bf[g], vb + p_off + (uint32_t)(ks * 16 * 144 + g * 32));
                #pragma unroll
                for (int j = 0; j < 8; j++)
                    mma_f16(O[j], a, bf[j >> 1] + (j & 1) * 2);
            }
        };

        for (int kt = 0; kt < nkt; kt++) {
            if (kt + 1 < nkt)
                issue_kv(kt + 1, (kt & 1) ? kb0 : kb1, (kt & 1) ? vb0 : vb1);
            compute(kt, kt >= nfull);
            if (kt + 1 < nkt) {
                CP_WAIT(0);
                __syncthreads();
            }
        }

        l0 += __shfl_xor_sync(0xffffffffu, l0, 1);
        l0 += __shfl_xor_sync(0xffffffffu, l0, 2);
        l1 += __shfl_xor_sync(0xffffffffu, l1, 1);
        l1 += __shfl_xor_sync(0xffffffffu, l1, 2);
        const float inv0 = 1.0f / l0;
        const float inv1 = 1.0f / l1;

        #pragma unroll
        for (int j = 0; j < 8; j++) {
            const int col = h * 64 + j * 8 + 2 * tig;
            *(uint32_t*)(out + ((size_t)b * LL + row0g) * DD + col) =
                pack_f16x2(O[j][0] * inv0, O[j][1] * inv0);
            *(uint32_t*)(out + ((size_t)b * LL + row0g + 8) * DD + col) =
                pack_f16x2(O[j][2] * inv1, O[j][3] * inv1);
        }

        // all warps must finish reading K/V/Q before the next tile reuses them
        __syncthreads();
    }
}

// ---------------------------------------------------------------------------
extern "C" void kernel_launch(void* const* d_in, const int* in_sizes, int n_in,
                              void* d_out, int out_size)
{
    const float* x     = (const float*)d_in[0];
    const float* w_in  = (const float*)d_in[1];
    const float* b_in  = (const float*)d_in[2];
    const float* w_out = (const float*)d_in[3];
    const float* b_out = (const float*)d_in[4];
    float* out = (float*)d_out;

    __half *xt, *qkv, *att, *wtin, *wtout;
    cudaGetSymbolAddress((void**)&xt, g_xt);
    cudaGetSymbolAddress((void**)&qkv, g_qkv);
    cudaGetSymbolAddress((void**)&att, g_att);
    cudaGetSymbolAddress((void**)&wtin, g_wtin);
    cudaGetSymbolAddress((void**)&wtout, g_wtout);

    const int M = BB * LL;
    const int GEMM_SMEM = 6 * 128 * 144;      // 110592
    const int ATTN_SMEM = 18432 + 4 * 9216;   // 55296
    static bool attr_set = false;
    if (!attr_set) {
        cudaFuncSetAttribute(gemm_f16_kernel,
                             cudaFuncAttributeMaxDynamicSharedMemorySize, GEMM_SMEM);
        cudaFuncSetAttribute(attn_f16_kernel,
                             cudaFuncAttributeMaxDynamicSharedMemorySize, ATTN_SMEM);
        attr_set = true;
    }

    // 0) Convert x to fp16; transpose+convert weights
    {
        int n4 = M * DD / 4;
        f32_to_f16_kernel<<<(n4 + 255) / 256, 256>>>(x, xt, n4);
        dim3 blk(32, 8);
        transpose_f16_kernel<<<dim3(3 * DD / 32, DD / 32), blk>>>(w_in, wtin, DD, 3 * DD);
        transpose_f16_kernel<<<dim3(DD / 32, DD / 32), blk>>>(w_out, wtout, DD, DD);
    }

    // 1) QKV projection (fp16 out)
    {
        dim3 grid(3 * DD / 128, M / 128);
        gemm_f16_kernel<<<grid, 256, GEMM_SMEM>>>(xt, wtin, b_in, nullptr, qkv,
                                                  M, 3 * DD, DD, 1);
    }

    // 2) Fused causal ALiBi attention — paired tiles, single balanced wave
    {
        dim3 grid(LL / 256, BB * HH);   // 8 x 32 = 256 CTAs
        attn_f16_kernel<<<grid, 256, ATTN_SMEM>>>(qkv, att);
    }

    // 3) Output projection (fp32 out)
    {
        dim3 grid(DD / 128, M / 128);
        gemm_f16_kernel<<<grid, 256, GEMM_SMEM>>>(att, wtout, b_out, out, nullptr,
                                                  M, DD, DD, 0);
    }
}